// round 17
// baseline (speedup 1.0000x reference)
#include <cuda_runtime.h>
#include <math.h>

#define STEPS 2048
#define BATCH 512
#define NBLK  128
#define THREADS 512

typedef unsigned long long u64;

__device__ float g_baseflow[BATCH];

// ---------------------------------------------------------------------------
__device__ __forceinline__ u64 pack2(float lo, float hi) {
    u64 r; asm("mov.b64 %0, {%1, %2};" : "=l"(r) : "f"(lo), "f"(hi)); return r;
}
__device__ __forceinline__ void fma2(u64& acc, u64 a, u64 b) {
    asm("fma.rn.f32x2 %0, %1, %2, %0;" : "+l"(acc) : "l"(a), "l"(b));
}
__device__ __forceinline__ float fast_sigmoid(float v) {
    return __fdividef(1.0f, 1.0f + __expf(-v));
}

// ---------------------------------------------------------------------------
// Kernel 1: per-batch-element 25th percentile of flow (bitonic sort)
// ---------------------------------------------------------------------------
__global__ void baseflow_kernel(const float* __restrict__ hyd) {
    __shared__ float v[STEPS];
    const int b = blockIdx.x;
    const int tid = threadIdx.x;
    for (int t = tid; t < STEPS; t += blockDim.x)
        v[t] = hyd[(t * BATCH + b) * 17];
    __syncthreads();
    for (int k = 2; k <= STEPS; k <<= 1) {
        for (int j = k >> 1; j > 0; j >>= 1) {
            for (int i = tid; i < STEPS; i += blockDim.x) {
                int l = i ^ j;
                if (l > i) {
                    float a = v[i], c = v[l];
                    bool up = ((i & k) == 0);
                    if ((a > c) == up) { v[i] = c; v[l] = a; }
                }
            }
            __syncthreads();
        }
    }
    if (tid == 0)
        g_baseflow[b] = 0.25f * v[511] + 0.75f * v[512];   // pos = 511.75
}

// ---------------------------------------------------------------------------
// SMEM (~36 KB, static)
// ---------------------------------------------------------------------------
struct __align__(16) Smem {
    float part1[4 * 512];    // [q][j][s] flat: q*512 + j*4 + s
    float part2[4 * 384];    // [q][j][s] flat (j padded to 96)
    float hA[512];           // [j][s]
    float hB[512];           // [j][s]
    float l0p[512];          // [j][s]
    float xin[64];           // [i][s]
    float outg[4 * 80];      // [s][col] sigmoided gates
    float lgt[4 * 16];       // [s][j] exp(logit)
    float st[32];            // [s][k]
    float w0sp[8 * 128];     // 0.01*W0 stores-part [k][j]
    float bflow_s[4];
};

// ---------------------------------------------------------------------------
// 512 threads = 16 warps, 4 samples, one CTA/SM, one wave.
// j = tid&127 owns unit j; q = tid>>7 owns k-slice [32q, 32q+32).
// Stages (4 barriers):
//  S1: layer1 partials + rain(t+1) prefetch
//  S2: combine1 -> hB ; stage x(t+1), LDG x(t+2)
//  S3: layer2 partials (j<89) || warps 3/7/11/15: l0x(t+1) -> l0p
//  S456 (warps 0-3 only; warp s = sample s):
//    combine2 (3 j/lane) ; sigmoids lane-spread ; exp(logits) lanes 0-8 ;
//    lane0 serial softmax-sum + mixing tail ; publish st ;
//    all lanes: hA(t+1) for sample s (4 units/lane, w0sp from SMEM)
// ---------------------------------------------------------------------------
__global__ void __launch_bounds__(THREADS, 1)
hyd_kernel(const float* __restrict__ hyd,
           const float* __restrict__ W0, const float* __restrict__ b0,
           const float* __restrict__ W1, const float* __restrict__ b1,
           const float* __restrict__ Wi, const float* __restrict__ bi,
           const float* __restrict__ Wo, const float* __restrict__ bo,
           float* __restrict__ out)
{
    __shared__ Smem S;
    const int tid  = threadIdx.x;
    const int j    = tid & 127;
    const int q    = tid >> 7;
    const int lane = tid & 31;
    const int warp = tid >> 5;
    const int blk  = blockIdx.x;

    // ---- register-resident weights / biases ----
    float w1r[32], wcr[32];
    float b1R = (q == 0) ? b1[j] : 0.f;
    float bcR = 0.f;
    #pragma unroll
    for (int k = 0; k < 32; k++) w1r[k] = W1[j * 128 + q * 32 + k];
    if (j < 9) {
        if (q == 0) bcR = bi[j];
        #pragma unroll
        for (int k = 0; k < 32; k++) wcr[k] = Wi[j * 128 + q * 32 + k];
    } else if (j < 89) {
        if (q == 0) bcR = bo[j - 9];
        #pragma unroll
        for (int k = 0; k < 32; k++) wcr[k] = Wo[(j - 9) * 128 + q * 32 + k];
    } else {
        #pragma unroll
        for (int k = 0; k < 32; k++) wcr[k] = 0.f;
    }
    // l0x role (warps 3/7/11/15): unit q*32+lane
    float w0tR[16], b0R = 0.f;
    if ((warp & 3) == 3) {
        int jj = q * 32 + lane;
        b0R = b0[jj];
        #pragma unroll
        for (int i = 0; i < 16; i++) w0tR[i] = W0[jj * 24 + i];
    }
    // SMEM stores-part weights [k][j]
    for (int idx = tid; idx < 8 * 128; idx += THREADS) {
        int k = idx >> 7, jj = idx & 127;
        S.w0sp[idx] = 0.01f * W0[jj * 24 + 16 + k];
    }

    // per-warp roles
    const int bsample = blk * 4 + warp;          // warps 0-3: epilogue sample
    const int xsample = blk * 4 + (warp - 8);    // warps 8-11: x prefetch
    float rain_cur = 0.f, rain_next = 0.f, xreg = 0.f;

    if (warp < 4 && lane == 0) rain_cur = hyd[bsample * 17 + 1];
    if (warp < 4 && lane < 4)  S.bflow_s[lane] = g_baseflow[blk * 4 + lane];
    if (warp >= 8 && warp < 12 && lane < 16) {
        S.xin[lane * 4 + (warp - 8)] = hyd[xsample * 17 + 1 + lane];    // x(0)
        xreg = hyd[(1 * BATCH + xsample) * 17 + 1 + lane];              // x(1)
    }
    if (tid < 32) S.st[tid] = ((tid & 7) == 1) ? 1.0f : 0.0f;
    __syncthreads();

    // ---- bootstrap: l0p(0) ----
    if ((warp & 3) == 3) {
        int jj = q * 32 + lane;
        u64 a01 = pack2(b0R, b0R), a23 = a01;
        #pragma unroll
        for (int i = 0; i < 16; i++) {
            ulonglong2 h = *(const ulonglong2*)&S.xin[i * 4];
            u64 wd = pack2(w0tR[i], w0tR[i]);
            fma2(a01, h.x, wd); fma2(a23, h.y, wd);
        }
        ulonglong2 pv; pv.x = a01; pv.y = a23;
        *(ulonglong2*)&S.l0p[jj * 4] = pv;
    }
    __syncthreads();
    // ---- bootstrap: hA(0) (all 512 threads, one (j,s) each) ----
    {
        int s = tid & 3;
        int jj = tid >> 2;
        float v = S.l0p[jj * 4 + s];
        #pragma unroll
        for (int k = 0; k < 8; k++)
            v = fmaf(S.w0sp[k * 128 + jj], S.st[s * 8 + k], v);
        S.hA[jj * 4 + s] = fmaxf(v, 0.f);
    }
    __syncthreads();

    // persistent stores in lane 0 of warps 0-3
    float sv[8];
    #pragma unroll
    for (int k = 0; k < 8; k++) sv[k] = (k == 1) ? 1.0f : 0.0f;

    for (int t = 0; t < STEPS; t++) {
        // ======== S1: layer1 partials (+ rain prefetch) ========
        if (t + 1 < STEPS && warp < 4 && lane == 0)
            rain_next = hyd[((t + 1) * BATCH + bsample) * 17 + 1];
        {
            u64 a01 = pack2(b1R, b1R), a23 = a01;
            const float* hp = &S.hA[q * 128];
            #pragma unroll
            for (int k = 0; k < 32; k++) {
                u64 wd = pack2(w1r[k], w1r[k]);
                ulonglong2 h = *(const ulonglong2*)&hp[k * 4];
                fma2(a01, h.x, wd); fma2(a23, h.y, wd);
            }
            ulonglong2 pv; pv.x = a01; pv.y = a23;
            *(ulonglong2*)&S.part1[q * 512 + j * 4] = pv;
        }
        __syncthreads();

        // ======== S2: combine1 -> hB ; stage x(t+1), LDG x(t+2) ========
        {
            float v = S.part1[tid]        + S.part1[512 + tid]
                    + S.part1[1024 + tid] + S.part1[1536 + tid];
            S.hB[tid] = fmaxf(v, 0.f);
        }
        if (warp >= 8 && warp < 12 && lane < 16) {
            S.xin[lane * 4 + (warp - 8)] = xreg;   // x(t+1)
            if (t + 2 < STEPS)
                xreg = hyd[((t + 2) * BATCH + xsample) * 17 + 1 + lane];
        }
        __syncthreads();

        // ======== S3: layer2 partials || l0x(t+1) ========
        if ((warp & 3) == 3) {
            int jj = q * 32 + lane;
            u64 a01 = pack2(b0R, b0R), a23 = a01;
            #pragma unroll
            for (int i = 0; i < 16; i++) {
                ulonglong2 h = *(const ulonglong2*)&S.xin[i * 4];
                u64 wd = pack2(w0tR[i], w0tR[i]);
                fma2(a01, h.x, wd); fma2(a23, h.y, wd);
            }
            ulonglong2 pv; pv.x = a01; pv.y = a23;
            *(ulonglong2*)&S.l0p[jj * 4] = pv;
        } else if (j < 89) {
            u64 a01 = pack2(bcR, bcR), a23 = a01;
            const float* hp = &S.hB[q * 128];
            #pragma unroll
            for (int k = 0; k < 32; k++) {
                u64 wd = pack2(wcr[k], wcr[k]);
                ulonglong2 h = *(const ulonglong2*)&hp[k * 4];
                fma2(a01, h.x, wd); fma2(a23, h.y, wd);
            }
            ulonglong2 pv; pv.x = a01; pv.y = a23;
            *(ulonglong2*)&S.part2[q * 384 + j * 4] = pv;
        }
        __syncthreads();

        // ======== S456: merged tail (warps 0-3 only; warp s = sample s) ====
        if (warp < 4) {
            const int s = warp;
            // combine2 for this sample: j = lane, lane+32, lane+64
            int i0 = lane * 4 + s;
            float v0 = S.part2[i0]       + S.part2[384 + i0]
                     + S.part2[768 + i0] + S.part2[1152 + i0];
            int i1 = (lane + 32) * 4 + s;
            float v1 = S.part2[i1]       + S.part2[384 + i1]
                     + S.part2[768 + i1] + S.part2[1152 + i1];
            float v2 = 0.f;
            if (lane < 25) {
                int i2 = (lane + 64) * 4 + s;
                v2 = S.part2[i2]       + S.part2[384 + i2]
                   + S.part2[768 + i2] + S.part2[1152 + i2];
            }
            // sigmoids lane-spread ; exp(logits) lanes 0-8
            if (lane >= 9) S.outg[s * 80 + lane - 9] = fast_sigmoid(v0);
            else           S.lgt[s * 16 + lane] = __expf(v0);
            S.outg[s * 80 + lane + 23] = fast_sigmoid(v1);
            if (lane < 25) S.outg[s * 80 + lane + 55] = fast_sigmoid(v2);
            __syncwarp();

            // lane0 serial tail (no MUFU)
            if (lane == 0) {
                float4 ea = *(const float4*)&S.lgt[s * 16];       // e0..e3
                float4 eb = *(const float4*)&S.lgt[s * 16 + 4];   // e4..e7
                float  e8 = S.lgt[s * 16 + 8];
                float ssum = (((ea.x + ea.y) + (ea.z + ea.w))
                            + ((eb.x + eb.y) + (eb.z + eb.w))) + e8;
                float r2 = __fdividef(rain_cur, ssum);
                sv[0] += ea.y * r2; sv[1] += ea.z * r2; sv[2] += ea.w * r2;
                sv[3] += eb.x * r2; sv[4] += eb.y * r2; sv[5] += eb.z * r2;
                sv[6] += eb.w * r2; sv[7] += e8   * r2;

                const float* bb = &S.outg[s * 80];
                #pragma unroll
                for (int d = 0; d < 8; d++) {
                    float4 bv0 = *(const float4*)&bb[d * 8];
                    float4 bv1 = *(const float4*)&bb[d * 8 + 4];
                    float fb0 = bv0.x * sv[0], fb1 = bv0.y * sv[1];
                    float fb2 = bv0.z * sv[2], fb3 = bv0.w * sv[3];
                    float fb4 = bv1.x * sv[4], fb5 = bv1.y * sv[5];
                    float fb6 = bv1.z * sv[6], fb7 = bv1.w * sv[7];
                    float fsum = ((fb0 + fb1) + (fb2 + fb3))
                               + ((fb4 + fb5) + (fb6 + fb7));
                    sv[0] -= fb0; sv[1] -= fb1; sv[2] -= fb2; sv[3] -= fb3;
                    sv[4] -= fb4; sv[5] -= fb5; sv[6] -= fb6; sv[7] -= fb7;
                    sv[d] += fsum;
                }
                {   // escape
                    float4 ua = *(const float4*)&bb[64];
                    float4 ub = *(const float4*)&bb[68];
                    sv[0] -= ua.x * sv[0]; sv[1] -= ua.y * sv[1];
                    sv[2] -= ua.z * sv[2]; sv[3] -= ua.w * sv[3];
                    sv[4] -= ub.x * sv[4]; sv[5] -= ub.y * sv[5];
                    sv[6] -= ub.z * sv[6]; sv[7] -= ub.w * sv[7];
                }
                {   // flow distn
                    float4 f0 = *(const float4*)&bb[72];
                    float4 f1 = *(const float4*)&bb[76];
                    float fd0 = f0.x * sv[0], fd1 = f0.y * sv[1];
                    float fd2 = f0.z * sv[2], fd3 = f0.w * sv[3];
                    float fd4 = f1.x * sv[4], fd5 = f1.y * sv[5];
                    float fd6 = f1.z * sv[6], fd7 = f1.w * sv[7];
                    float flow = ((fd0 + fd1) + (fd2 + fd3))
                               + ((fd4 + fd5) + (fd6 + fd7));
                    sv[0] -= fd0; sv[1] -= fd1; sv[2] -= fd2; sv[3] -= fd3;
                    sv[4] -= fd4; sv[5] -= fd5; sv[6] -= fd6; sv[7] -= fd7;
                    out[t * BATCH + bsample] = flow;
                    if (t == 0)
                        sv[2] = S.bflow_s[s] / fmaxf(f0.z, 1e-5f);  // b_flow[SLOW]
                }
                *(float4*)&S.st[s * 8]     = make_float4(sv[0], sv[1], sv[2], sv[3]);
                *(float4*)&S.st[s * 8 + 4] = make_float4(sv[4], sv[5], sv[6], sv[7]);
                rain_cur = rain_next;
            }
            __syncwarp();

            // hA(t+1) finish for sample s: each lane does units lane+32m
            float4 s0 = *(const float4*)&S.st[s * 8];      // broadcast
            float4 s1 = *(const float4*)&S.st[s * 8 + 4];
            #pragma unroll
            for (int m = 0; m < 4; m++) {
                int jj = lane + 32 * m;
                float v = S.l0p[jj * 4 + s];
                v = fmaf(S.w0sp[0 * 128 + jj], s0.x, v);
                v = fmaf(S.w0sp[1 * 128 + jj], s0.y, v);
                v = fmaf(S.w0sp[2 * 128 + jj], s0.z, v);
                v = fmaf(S.w0sp[3 * 128 + jj], s0.w, v);
                v = fmaf(S.w0sp[4 * 128 + jj], s1.x, v);
                v = fmaf(S.w0sp[5 * 128 + jj], s1.y, v);
                v = fmaf(S.w0sp[6 * 128 + jj], s1.z, v);
                v = fmaf(S.w0sp[7 * 128 + jj], s1.w, v);
                S.hA[jj * 4 + s] = fmaxf(v, 0.f);
            }
        }
        __syncthreads();
    }
}

// ---------------------------------------------------------------------------
// Harness entry.  Inputs: hyd_input, W0, b0, W1, b1, W_in, b_in, W_out, b_out
// ---------------------------------------------------------------------------
extern "C" void kernel_launch(void* const* d_in, const int* in_sizes, int n_in,
                              void* d_out, int out_size) {
    const float* hyd = (const float*)d_in[0];
    const float* W0  = (const float*)d_in[1];
    const float* b0  = (const float*)d_in[2];
    const float* W1  = (const float*)d_in[3];
    const float* b1  = (const float*)d_in[4];
    const float* Wi  = (const float*)d_in[5];
    const float* bi  = (const float*)d_in[6];
    const float* Wo  = (const float*)d_in[7];
    const float* bo  = (const float*)d_in[8];
    float* out = (float*)d_out;

    baseflow_kernel<<<BATCH, 1024>>>(hyd);
    hyd_kernel<<<NBLK, THREADS>>>(hyd, W0, b0, W1, b1, Wi, bi, Wo, bo, out);
}